// round 5
// baseline (speedup 1.0000x reference)
#include <cuda_runtime.h>
#include <cuda_fp16.h>
#include <math_constants.h>
#include <cstdint>

#define Bn 128
#define Hn 128

__device__ float    g_scores[Bn * Bn];
__device__ unsigned g_cnt = 0;

// smem: A tile (fp16, 32KB) | B buf0 (32KB) | B buf1 (32KB) | rmax region (4KB)
#define A_OFF      0
#define B_OFF(b)   (32768 + (b) * 32768)
#define R_OFF      (3 * 32768)
#define SMEM_BYTES (3 * 32768 + 4096)

__device__ __forceinline__ uint32_t smem_u32(const void* p) {
    uint32_t a;
    asm("{ .reg .u64 t; cvta.to.shared.u64 t, %1; cvt.u32.u64 %0, t; }" : "=r"(a) : "l"(p));
    return a;
}
__device__ __forceinline__ void ldsm4(uint32_t& r0, uint32_t& r1, uint32_t& r2, uint32_t& r3,
                                      uint32_t addr) {
    asm volatile("ldmatrix.sync.aligned.m8n8.x4.shared.b16 {%0,%1,%2,%3}, [%4];"
                 : "=r"(r0), "=r"(r1), "=r"(r2), "=r"(r3) : "r"(addr));
}
__device__ __forceinline__ void mma16(float* d, const uint32_t* a, uint32_t b0, uint32_t b1) {
    asm volatile(
        "mma.sync.aligned.m16n8k16.row.col.f32.f16.f16.f32 "
        "{%0,%1,%2,%3}, {%4,%5,%6,%7}, {%8,%9}, {%0,%1,%2,%3};"
        : "+f"(d[0]), "+f"(d[1]), "+f"(d[2]), "+f"(d[3])
        : "r"(a[0]), "r"(a[1]), "r"(a[2]), "r"(a[3]), "r"(b0), "r"(b1));
}

// ---------------------------------------------------------------------------
// Staging: 128x128 fp32 tile -> fp16 smem. Row = 256B, 16B units XOR-swizzled
// by (row & 7). 512 threads; each pass moves half the tile via 4 float4/thread.
// ---------------------------------------------------------------------------
__device__ __forceinline__ void ldg4(const float4* __restrict__ g, int pass, int t, float4* st) {
    #pragma unroll
    for (int j = 0; j < 4; ++j) st[j] = g[pass * 2048 + j * 512 + t];
}
__device__ __forceinline__ void sts4(char* sm, int pass, int t, const float4* st) {
    #pragma unroll
    for (int j = 0; j < 4; ++j) {
        int idx = pass * 2048 + j * 512 + t;
        int row = idx >> 5, c4 = idx & 31;
        __half2 h0 = __floats2half2_rn(st[j].x, st[j].y);
        __half2 h1 = __floats2half2_rn(st[j].z, st[j].w);
        uint2 w;
        w.x = *reinterpret_cast<uint32_t*>(&h0);
        w.y = *reinterpret_cast<uint32_t*>(&h1);
        int off = row * 256 + (((c4 >> 1) ^ (row & 7)) << 4) + ((c4 & 1) << 3);
        *reinterpret_cast<uint2*>(sm + off) = w;
    }
}

// ---------------------------------------------------------------------------
// Fused kernel: 128 CTAs x 512 threads. CTA (mi=bid>>2, cg=bid&3).
// 16 warps: wm=wid>>2 (M=32 = one b), wn=wid&3 (N=32 quarter).
// A fragments register-resident across all 32 c-iterations.
// ---------------------------------------------------------------------------
extern "C" __global__ void __launch_bounds__(512, 1)
colbert_fused(const float* __restrict__ Q, const float* __restrict__ P, float* __restrict__ out)
{
    extern __shared__ __align__(128) char smem[];
    const uint32_t sbase = smem_u32(smem);

    const int t    = threadIdx.x;
    const int lane = t & 31;
    const int wid  = t >> 5;
    const int wm   = wid >> 2;      // 0..3  (b within the 4-b A stripe)
    const int wn   = wid & 3;       // 0..3  (n quarter)
    const int mi   = blockIdx.x >> 2;
    const int cg   = blockIdx.x & 3;
    const int gid  = lane >> 2;
    const int tig  = lane & 3;

    // ---- stage A tile and B tile for first c
    float4 st[4];
    {
        const float4* Qg = reinterpret_cast<const float4*>(Q + (size_t)mi * 128 * Hn);
        ldg4(Qg, 0, t, st); sts4(smem + A_OFF, 0, t, st);
        ldg4(Qg, 1, t, st); sts4(smem + A_OFF, 1, t, st);
    }
    const float4* Pg = reinterpret_cast<const float4*>(P);
    {
        const float4* g0 = Pg + (size_t)(cg * 32) * 4096;
        ldg4(g0, 0, t, st); sts4(smem + B_OFF(0), 0, t, st);
        ldg4(g0, 1, t, st); sts4(smem + B_OFF(0), 1, t, st);
    }
    __syncthreads();

    // ---- A fragments into registers (once, reused for all 32 c's)
    uint32_t aF[2][8][4];
    {
        const int rA = wm * 32 + (lane & 15);
        const int kqA = lane >> 4;
        #pragma unroll
        for (int mt = 0; mt < 2; ++mt) {
            const int row = rA + mt * 16;
            const uint32_t rowbase = sbase + A_OFF + row * 256;
            #pragma unroll
            for (int ks = 0; ks < 8; ++ks) {
                uint32_t addr = rowbase + (((2 * ks + kqA) ^ (row & 7)) << 4);
                ldsm4(aF[mt][ks][0], aF[mt][ks][1], aF[mt][ks][2], aF[mt][ks][3], addr);
            }
        }
    }

    const int rBl = (lane & 7) + ((lane >> 4) << 3);
    const int kqB = (lane >> 3) & 1;

    for (int i = 0; i < 32; ++i) {
        const int c = cg * 32 + i;
        const uint32_t Bbase = sbase + B_OFF(i & 1);
        char* Bnxt = smem + B_OFF(1 - (i & 1));
        const bool pre = (i + 1 < 32);
        const float4* gn = Pg + (size_t)(c + 1) * 4096;

        float acc[2][4][4];
        #pragma unroll
        for (int mt = 0; mt < 2; ++mt)
            #pragma unroll
            for (int nt = 0; nt < 4; ++nt)
                #pragma unroll
                for (int r = 0; r < 4; ++r) acc[mt][nt][r] = 0.0f;

        if (pre) ldg4(gn, 0, t, st);

        #pragma unroll
        for (int ks = 0; ks < 8; ++ks) {
            uint32_t bF[2][4];
            #pragma unroll
            for (int np = 0; np < 2; ++np) {
                const int row = wn * 32 + np * 16 + rBl;
                uint32_t addr = Bbase + row * 256 + (((2 * ks + kqB) ^ (row & 7)) << 4);
                ldsm4(bF[np][0], bF[np][1], bF[np][2], bF[np][3], addr);
            }
            #pragma unroll
            for (int np = 0; np < 2; ++np)
                #pragma unroll
                for (int mt = 0; mt < 2; ++mt) {
                    mma16(acc[mt][2 * np],     aF[mt][ks], bF[np][0], bF[np][1]);
                    mma16(acc[mt][2 * np + 1], aF[mt][ks], bF[np][2], bF[np][3]);
                }
            if (ks == 3 && pre) { sts4(Bnxt, 0, t, st); ldg4(gn, 1, t, st); }
        }
        if (pre) sts4(Bnxt, 1, t, st);

        // ---- epilogue: per-row max over this warp's 32 n-cols -> rbuf
        float* rbuf = reinterpret_cast<float*>(smem + R_OFF) + ((i & 1) * 4 + wn) * 128;
        #pragma unroll
        for (int mt = 0; mt < 2; ++mt) {
            float m0 = acc[mt][0][0], m1 = acc[mt][0][2];
            #pragma unroll
            for (int nt = 0; nt < 4; ++nt) {
                m0 = fmaxf(m0, fmaxf(acc[mt][nt][0], acc[mt][nt][1]));
                m1 = fmaxf(m1, fmaxf(acc[mt][nt][2], acc[mt][nt][3]));
            }
            m0 = fmaxf(m0, __shfl_xor_sync(0xffffffffu, m0, 1));
            m0 = fmaxf(m0, __shfl_xor_sync(0xffffffffu, m0, 2));
            m1 = fmaxf(m1, __shfl_xor_sync(0xffffffffu, m1, 1));
            m1 = fmaxf(m1, __shfl_xor_sync(0xffffffffu, m1, 2));
            if (tig == 0) {
                rbuf[wm * 32 + mt * 16 + gid]     = m0;
                rbuf[wm * 32 + mt * 16 + 8 + gid] = m1;
            }
        }
        __syncthreads();

        // ---- combine 4 n-quarters, sum over s, write score (wn==0 warps)
        if (wn == 0) {
            const float* r0 = reinterpret_cast<const float*>(smem + R_OFF) + (i & 1) * 4 * 128;
            float v = fmaxf(fmaxf(r0[wm * 32 + lane], r0[128 + wm * 32 + lane]),
                            fmaxf(r0[256 + wm * 32 + lane], r0[384 + wm * 32 + lane]));
            #pragma unroll
            for (int off = 16; off; off >>= 1) v += __shfl_xor_sync(0xffffffffu, v, off);
            if (lane == 0) g_scores[(mi * 4 + wm) * Bn + c] = v;
        }
    }

    // ---- last CTA computes the loss
    __syncthreads();
    __threadfence();
    __shared__ unsigned s_rank;
    if (t == 0) s_rank = atomicAdd(&g_cnt, 1);
    __syncthreads();
    if (s_rank != 127) return;
    if (t == 0) atomicExch(&g_cnt, 0);   // reset for graph replay
    __threadfence();

    const int row = t >> 2, j = t & 3;   // 4 threads per row, 32 cols each
    const float4* rp = reinterpret_cast<const float4*>(&g_scores[row * Bn + j * 32]);
    float m = -CUDART_INF_F, diag = 0.0f;
    #pragma unroll
    for (int k4 = 0; k4 < 8; ++k4) {
        float4 v = rp[k4];
        m = fmaxf(m, fmaxf(fmaxf(v.x, v.y), fmaxf(v.z, v.w)));
        int cb = j * 32 + k4 * 4;
        if (row == cb + 0) diag = v.x;
        if (row == cb + 1) diag = v.y;
        if (row == cb + 2) diag = v.z;
        if (row == cb + 3) diag = v.w;
    }
    m = fmaxf(m, __shfl_xor_sync(0xffffffffu, m, 1));
    m = fmaxf(m, __shfl_xor_sync(0xffffffffu, m, 2));
    diag += __shfl_xor_sync(0xffffffffu, diag, 1);
    diag += __shfl_xor_sync(0xffffffffu, diag, 2);

    float s = 0.0f;
    #pragma unroll
    for (int k4 = 0; k4 < 8; ++k4) {
        float4 v = rp[k4];
        s += expf(50.0f * (v.x - m)) + expf(50.0f * (v.y - m)) +
             expf(50.0f * (v.z - m)) + expf(50.0f * (v.w - m));
    }
    s += __shfl_xor_sync(0xffffffffu, s, 1);
    s += __shfl_xor_sync(0xffffffffu, s, 2);

    float* sred = reinterpret_cast<float*>(smem + R_OFF);
    if (j == 0) sred[row] = 50.0f * diag - (50.0f * m + logf(s));
    __syncthreads();
    if (t < 128) {
        float v = sred[t];
        #pragma unroll
        for (int off = 16; off; off >>= 1) v += __shfl_xor_sync(0xffffffffu, v, off);
        if ((t & 31) == 0) sred[512 + (t >> 5)] = v;
    }
    __syncthreads();
    if (t == 0) out[0] = -(sred[512] + sred[513] + sred[514] + sred[515]) / 128.0f;
}

// ---------------------------------------------------------------------------
extern "C" void kernel_launch(void* const* d_in, const int* in_sizes, int n_in,
                              void* d_out, int out_size)
{
    const float* Q = (const float*)d_in[0];  // [128, 32, 128]
    const float* P = (const float*)d_in[1];  // [128, 128, 128]
    float* out = (float*)d_out;

    cudaFuncSetAttribute(colbert_fused,
                         cudaFuncAttributeMaxDynamicSharedMemorySize, SMEM_BYTES);
    colbert_fused<<<128, 512, SMEM_BYTES>>>(Q, P, out);
}

// round 6
// speedup vs baseline: 1.4041x; 1.4041x over previous
#include <cuda_runtime.h>
#include <cuda_fp16.h>
#include <math_constants.h>
#include <cstdint>

#define Bn 128
#define Hn 128

__device__ float    g_scores[Bn * Bn];
__device__ unsigned g_cnt = 0;
// Pre-converted, pre-swizzled fp16 tiles (tile = 128 rows x 256B swizzled)
__device__ __align__(16) char g_Qh[32 * 32768];    // 1MB: 32 mi-tiles
__device__ __align__(16) char g_Ph[128 * 32768];   // 4MB: 128 c-tiles

// smem: A tile (32KB) | B buf0 (32KB) | B buf1 (32KB) | reduce region (4KB)
#define A_OFF      0
#define B_OFF(b)   (32768 + (b) * 32768)
#define R_OFF      (3 * 32768)
#define SMEM_BYTES (3 * 32768 + 4096)

__device__ __forceinline__ uint32_t smem_u32(const void* p) {
    uint32_t a;
    asm("{ .reg .u64 t; cvta.to.shared.u64 t, %1; cvt.u32.u64 %0, t; }" : "=r"(a) : "l"(p));
    return a;
}
__device__ __forceinline__ void cp16(uint32_t sm, const void* g) {
    asm volatile("cp.async.cg.shared.global [%0], [%1], 16;" :: "r"(sm), "l"(g));
}
#define CP_COMMIT() asm volatile("cp.async.commit_group;" ::: "memory")
#define CP_WAIT(n)  asm volatile("cp.async.wait_group %0;" :: "n"(n) : "memory")

__device__ __forceinline__ void ldsm4(uint32_t& r0, uint32_t& r1, uint32_t& r2, uint32_t& r3,
                                      uint32_t addr) {
    asm volatile("ldmatrix.sync.aligned.m8n8.x4.shared.b16 {%0,%1,%2,%3}, [%4];"
                 : "=r"(r0), "=r"(r1), "=r"(r2), "=r"(r3) : "r"(addr));
}
__device__ __forceinline__ void mma16(float* d, const uint32_t* a, uint32_t b0, uint32_t b1) {
    asm volatile(
        "mma.sync.aligned.m16n8k16.row.col.f32.f16.f16.f32 "
        "{%0,%1,%2,%3}, {%4,%5,%6,%7}, {%8,%9}, {%0,%1,%2,%3};"
        : "+f"(d[0]), "+f"(d[1]), "+f"(d[2]), "+f"(d[3])
        : "r"(a[0]), "r"(a[1]), "r"(a[2]), "r"(a[3]), "r"(b0), "r"(b1));
}

// ---------------------------------------------------------------------------
// Pre-kernel: fp32 [128rows x 128] tile -> fp16 swizzled tile (row*256B,
// 16B unit u at ((u ^ (row&7))<<4)). Blocks 0..127: P tile c. 128..159: Q mi.
// ---------------------------------------------------------------------------
extern "C" __global__ void __launch_bounds__(256)
colbert_convert(const float* __restrict__ Q, const float* __restrict__ P)
{
    const int bid = blockIdx.x, t = threadIdx.x;
    const float4* src;
    char* dst;
    if (bid < 128) { src = reinterpret_cast<const float4*>(P) + (size_t)bid * 4096; dst = g_Ph + (size_t)bid * 32768; }
    else           { src = reinterpret_cast<const float4*>(Q) + (size_t)(bid - 128) * 4096; dst = g_Qh + (size_t)(bid - 128) * 32768; }
    #pragma unroll
    for (int j = 0; j < 16; ++j) {
        int f4 = j * 256 + t;
        float4 v = src[f4];
        int row = f4 >> 5, c4 = f4 & 31;
        __half2 h0 = __floats2half2_rn(v.x, v.y);
        __half2 h1 = __floats2half2_rn(v.z, v.w);
        uint2 w;
        w.x = *reinterpret_cast<uint32_t*>(&h0);
        w.y = *reinterpret_cast<uint32_t*>(&h1);
        int off = row * 256 + ((((c4 >> 1) ^ (row & 7))) << 4) + ((c4 & 1) << 3);
        *reinterpret_cast<uint2*>(dst + off) = w;
    }
}

// ---------------------------------------------------------------------------
// Main kernel: 128 CTAs x 256 threads (8 warps: wm=wid>>1 b-stripe, wn=wid&1
// n-half). A frags register-resident; B staged by cp.async, depth-2 pipeline;
// bF double-buffered across k-steps. Last CTA computes the loss.
// ---------------------------------------------------------------------------
extern "C" __global__ void __launch_bounds__(256, 1)
colbert_fused(float* __restrict__ out)
{
    extern __shared__ __align__(128) char smem[];
    const uint32_t sbase = smem_u32(smem);

    const int t    = threadIdx.x;
    const int lane = t & 31;
    const int wid  = t >> 5;
    const int wm   = wid >> 1;
    const int wn   = wid & 1;
    const int mi   = blockIdx.x >> 2;
    const int cg   = blockIdx.x & 3;
    const int gid  = lane >> 2;
    const int tig  = lane & 3;

    // ---- prologue: async-stage A + B0 (group0), B1 (group1)
    {
        const char* gA = g_Qh + (size_t)mi * 32768;
        const char* gB = g_Ph + (size_t)(cg * 32) * 32768;
        #pragma unroll
        for (int j = 0; j < 8; ++j) {
            int off = j * 4096 + t * 16;
            cp16(sbase + A_OFF + off, gA + off);
            cp16(sbase + B_OFF(0) + off, gB + off);
        }
        CP_COMMIT();
        const char* gB1 = gB + 32768;
        #pragma unroll
        for (int j = 0; j < 8; ++j) {
            int off = j * 4096 + t * 16;
            cp16(sbase + B_OFF(1) + off, gB1 + off);
        }
        CP_COMMIT();
    }
    CP_WAIT(1);
    __syncthreads();

    // ---- A fragments -> registers (reused for all 32 c's)
    uint32_t aF[2][8][4];
    {
        const int rA = wm * 32 + (lane & 15);
        const int kqA = lane >> 4;
        #pragma unroll
        for (int mt = 0; mt < 2; ++mt) {
            const int row = rA + mt * 16;
            const uint32_t rowbase = sbase + A_OFF + row * 256;
            #pragma unroll
            for (int ks = 0; ks < 8; ++ks) {
                uint32_t addr = rowbase + (((2 * ks + kqA) ^ (row & 7)) << 4);
                ldsm4(aF[mt][ks][0], aF[mt][ks][1], aF[mt][ks][2], aF[mt][ks][3], addr);
            }
        }
    }

    const int rBl = (lane & 7) + ((lane >> 4) << 3);
    const int kqB = (lane >> 3) & 1;
    const int rowB0 = wn * 64 + rBl;          // np=0 row
    const int rowB1 = wn * 64 + 16 + rBl;     // np=1 row
    const int rowB2 = wn * 64 + 32 + rBl;
    const int rowB3 = wn * 64 + 48 + rBl;

    for (int i = 0; i < 32; ++i) {
        const int c = cg * 32 + i;
        const uint32_t Bbase = sbase + B_OFF(i & 1);

        float acc[2][8][4];
        #pragma unroll
        for (int mt = 0; mt < 2; ++mt)
            #pragma unroll
            for (int nt = 0; nt < 8; ++nt)
                #pragma unroll
                for (int r = 0; r < 4; ++r) acc[mt][nt][r] = 0.0f;

        // bF double buffer: [buf][np(4)][4regs] -> keep 2 np-pairs per buf
        uint32_t bF[2][4][4];
        {
            uint32_t a0 = Bbase + rowB0 * 256 + ((kqB ^ (rowB0 & 7)) << 4);
            uint32_t a1 = Bbase + rowB1 * 256 + ((kqB ^ (rowB1 & 7)) << 4);
            uint32_t a2 = Bbase + rowB2 * 256 + ((kqB ^ (rowB2 & 7)) << 4);
            uint32_t a3 = Bbase + rowB3 * 256 + ((kqB ^ (rowB3 & 7)) << 4);
            ldsm4(bF[0][0][0], bF[0][0][1], bF[0][0][2], bF[0][0][3], a0);
            ldsm4(bF[0][1][0], bF[0][1][1], bF[0][1][2], bF[0][1][3], a1);
            ldsm4(bF[0][2][0], bF[0][2][1], bF[0][2][2], bF[0][2][3], a2);
            ldsm4(bF[0][3][0], bF[0][3][1], bF[0][3][2], bF[0][3][3], a3);
        }
        #pragma unroll
        for (int ks = 0; ks < 8; ++ks) {
            const int cur = ks & 1, nxt = cur ^ 1;
            if (ks < 7) {
                const int ku = 2 * (ks + 1) + kqB;
                uint32_t a0 = Bbase + rowB0 * 256 + ((ku ^ (rowB0 & 7)) << 4);
                uint32_t a1 = Bbase + rowB1 * 256 + ((ku ^ (rowB1 & 7)) << 4);
                uint32_t a2 = Bbase + rowB2 * 256 + ((ku ^ (rowB2 & 7)) << 4);
                uint32_t a3 = Bbase + rowB3 * 256 + ((ku ^ (rowB3 & 7)) << 4);
                ldsm4(bF[nxt][0][0], bF[nxt][0][1], bF[nxt][0][2], bF[nxt][0][3], a0);
                ldsm4(bF[nxt][1][0], bF[nxt][1][1], bF[nxt][1][2], bF[nxt][1][3], a1);
                ldsm4(bF[nxt][2][0], bF[nxt][2][1], bF[nxt][2][2], bF[nxt][2][3], a2);
                ldsm4(bF[nxt][3][0], bF[nxt][3][1], bF[nxt][3][2], bF[nxt][3][3], a3);
            }
            #pragma unroll
            for (int np = 0; np < 4; ++np)
                #pragma unroll
                for (int mt = 0; mt < 2; ++mt) {
                    mma16(acc[mt][2 * np],     aF[mt][ks], bF[cur][np][0], bF[cur][np][1]);
                    mma16(acc[mt][2 * np + 1], aF[mt][ks], bF[cur][np][2], bF[cur][np][3]);
                }
        }

        // ---- epilogue: per-row max over this warp's 64 n-cols
        float* rbuf = reinterpret_cast<float*>(smem + R_OFF) + ((i & 1) * 2 + wn) * 128;
        #pragma unroll
        for (int mt = 0; mt < 2; ++mt) {
            float m0 = acc[mt][0][0], m1 = acc[mt][0][2];
            #pragma unroll
            for (int nt = 0; nt < 8; ++nt) {
                m0 = fmaxf(m0, fmaxf(acc[mt][nt][0], acc[mt][nt][1]));
                m1 = fmaxf(m1, fmaxf(acc[mt][nt][2], acc[mt][nt][3]));
            }
            m0 = fmaxf(m0, __shfl_xor_sync(0xffffffffu, m0, 1));
            m0 = fmaxf(m0, __shfl_xor_sync(0xffffffffu, m0, 2));
            m1 = fmaxf(m1, __shfl_xor_sync(0xffffffffu, m1, 1));
            m1 = fmaxf(m1, __shfl_xor_sync(0xffffffffu, m1, 2));
            if (tig == 0) {
                rbuf[wm * 32 + mt * 16 + gid]     = m0;
                rbuf[wm * 32 + mt * 16 + 8 + gid] = m1;
            }
        }
        __syncthreads();  // rbuf ready; all warps done reading buf i&1

        if (wn == 0) {
            const float* r0 = reinterpret_cast<const float*>(smem + R_OFF) + (i & 1) * 2 * 128;
            const float* r1 = r0 + 128;
            float v = fmaxf(r0[wm * 32 + lane], r1[wm * 32 + lane]);
            #pragma unroll
            for (int off = 16; off; off >>= 1) v += __shfl_xor_sync(0xffffffffu, v, off);
            if (lane == 0) g_scores[(mi * 4 + wm) * Bn + c] = v;
        }

        // ---- refill buf i&1 with c+2, then wait for c+1's data
        if (i + 2 < 32) {
            const char* gB = g_Ph + (size_t)(c + 2) * 32768;
            #pragma unroll
            for (int j = 0; j < 8; ++j) {
                int off = j * 4096 + t * 16;
                cp16(sbase + B_OFF(i & 1) + off, gB + off);
            }
            CP_COMMIT();
        }
        if (i + 1 < 32) {
            if (i + 2 < 32) CP_WAIT(1); else CP_WAIT(0);
            __syncthreads();
        }
    }

    // ---- last CTA computes the loss
    __syncthreads();
    __threadfence();
    __shared__ unsigned s_rank;
    if (t == 0) s_rank = atomicAdd(&g_cnt, 1);
    __syncthreads();
    if (s_rank != 127) return;
    if (t == 0) atomicExch(&g_cnt, 0);
    __threadfence();

    const int row = t >> 1, j = t & 1;
    const float4* rp = reinterpret_cast<const float4*>(&g_scores[row * Bn + j * 64]);
    float m = -CUDART_INF_F, diag = 0.0f;
    #pragma unroll
    for (int k4 = 0; k4 < 16; ++k4) {
        float4 v = rp[k4];
        m = fmaxf(m, fmaxf(fmaxf(v.x, v.y), fmaxf(v.z, v.w)));
        int cb = j * 64 + k4 * 4;
        if (row == cb + 0) diag = v.x;
        if (row == cb + 1) diag = v.y;
        if (row == cb + 2) diag = v.z;
        if (row == cb + 3) diag = v.w;
    }
    m = fmaxf(m, __shfl_xor_sync(0xffffffffu, m, 1));
    diag += __shfl_xor_sync(0xffffffffu, diag, 1);

    float s = 0.0f;
    #pragma unroll
    for (int k4 = 0; k4 < 16; ++k4) {
        float4 v = rp[k4];
        s += expf(50.0f * (v.x - m)) + expf(50.0f * (v.y - m)) +
             expf(50.0f * (v.z - m)) + expf(50.0f * (v.w - m));
    }
    s += __shfl_xor_sync(0xffffffffu, s, 1);

    float* sred = reinterpret_cast<float*>(smem + R_OFF);
    if (j == 0) sred[row] = 50.0f * diag - (50.0f * m + logf(s));
    __syncthreads();
    if (t < 128) {
        float v = sred[t];
        #pragma unroll
        for (int off = 16; off; off >>= 1) v += __shfl_xor_sync(0xffffffffu, v, off);
        if ((t & 31) == 0) sred[256 + (t >> 5)] = v;
    }
    __syncthreads();
    if (t == 0) out[0] = -(sred[256] + sred[257] + sred[258] + sred[259]) / 128.0f;
}

// ---------------------------------------------------------------------------
extern "C" void kernel_launch(void* const* d_in, const int* in_sizes, int n_in,
                              void* d_out, int out_size)
{
    const float* Q = (const float*)d_in[0];  // [128, 32, 128]
    const float* P = (const float*)d_in[1];  // [128, 128, 128]
    float* out = (float*)d_out;

    cudaFuncSetAttribute(colbert_fused,
                         cudaFuncAttributeMaxDynamicSharedMemorySize, SMEM_BYTES);
    colbert_convert<<<160, 256>>>(Q, P);
    colbert_fused<<<128, 256, SMEM_BYTES>>>(out);
}

// round 7
// speedup vs baseline: 1.4474x; 1.0309x over previous
#include <cuda_runtime.h>
#include <cuda_fp16.h>
#include <math_constants.h>
#include <cstdint>

#define Bn 128
#define Hn 128

__device__ float    g_scores[Bn * Bn];
__device__ unsigned g_cnt = 0;
// Pre-converted, pre-swizzled fp16 tiles (tile = 128 rows x 256B swizzled)
__device__ __align__(16) char g_Qh[32 * 32768];    // 1MB: 32 mi-tiles
__device__ __align__(16) char g_Ph[128 * 32768];   // 4MB: 128 c-tiles

// smem: A half-tile (16KB) | B buf0 (32KB) | B buf1 (32KB) | rmax (16KB)
#define A_OFF      0
#define B_OFF(b)   (16384 + (b) * 32768)
#define RM_OFF     (16384 + 2 * 32768)
#define SMEM_BYTES (16384 + 2 * 32768 + 16384)

__device__ __forceinline__ uint32_t smem_u32(const void* p) {
    uint32_t a;
    asm("{ .reg .u64 t; cvta.to.shared.u64 t, %1; cvt.u32.u64 %0, t; }" : "=r"(a) : "l"(p));
    return a;
}
__device__ __forceinline__ void cp16(uint32_t sm, const void* g) {
    asm volatile("cp.async.cg.shared.global [%0], [%1], 16;" :: "r"(sm), "l"(g));
}
#define CP_COMMIT() asm volatile("cp.async.commit_group;" ::: "memory")
#define CP_WAIT(n)  asm volatile("cp.async.wait_group %0;" :: "n"(n) : "memory")

__device__ __forceinline__ void ldsm4(uint32_t& r0, uint32_t& r1, uint32_t& r2, uint32_t& r3,
                                      uint32_t addr) {
    asm volatile("ldmatrix.sync.aligned.m8n8.x4.shared.b16 {%0,%1,%2,%3}, [%4];"
                 : "=r"(r0), "=r"(r1), "=r"(r2), "=r"(r3) : "r"(addr));
}
__device__ __forceinline__ void mma16(float* d, const uint32_t* a, uint32_t b0, uint32_t b1) {
    asm volatile(
        "mma.sync.aligned.m16n8k16.row.col.f32.f16.f16.f32 "
        "{%0,%1,%2,%3}, {%4,%5,%6,%7}, {%8,%9}, {%0,%1,%2,%3};"
        : "+f"(d[0]), "+f"(d[1]), "+f"(d[2]), "+f"(d[3])
        : "r"(a[0]), "r"(a[1]), "r"(a[2]), "r"(a[3]), "r"(b0), "r"(b1));
}

// ---------------------------------------------------------------------------
// Pre-kernel: fp32 [128 x 128] tile -> fp16 swizzled (row*256B, unit^(row&7)).
// ---------------------------------------------------------------------------
extern "C" __global__ void __launch_bounds__(256)
colbert_convert(const float* __restrict__ Q, const float* __restrict__ P)
{
    const int bid = blockIdx.x, t = threadIdx.x;
    const float4* src;
    char* dst;
    if (bid < 128) { src = reinterpret_cast<const float4*>(P) + (size_t)bid * 4096; dst = g_Ph + (size_t)bid * 32768; }
    else           { src = reinterpret_cast<const float4*>(Q) + (size_t)(bid - 128) * 4096; dst = g_Qh + (size_t)(bid - 128) * 32768; }
    #pragma unroll
    for (int j = 0; j < 16; ++j) {
        int f4 = j * 256 + t;
        float4 v = src[f4];
        int row = f4 >> 5, c4 = f4 & 31;
        __half2 h0 = __floats2half2_rn(v.x, v.y);
        __half2 h1 = __floats2half2_rn(v.z, v.w);
        uint2 w;
        w.x = *reinterpret_cast<uint32_t*>(&h0);
        w.y = *reinterpret_cast<uint32_t*>(&h1);
        int off = row * 256 + ((((c4 >> 1) ^ (row & 7))) << 4) + ((c4 & 1) << 3);
        *reinterpret_cast<uint2*>(dst + off) = w;
    }
}

// ---------------------------------------------------------------------------
// Main: 256 CTAs x 128 threads, 2 CTAs/SM. CTA (mi2=bid>>2: 64 A-rows, cg=bid&3).
// 4 warps: wm=wid>>1 (M=32 = one b), wn=wid&1 (N=64 half).
// Per-iter: MMA + private rmax write + ONE barrier. Combine after the loop.
// ---------------------------------------------------------------------------
extern "C" __global__ void __launch_bounds__(128, 2)
colbert_fused(float* __restrict__ out)
{
    extern __shared__ __align__(128) char smem[];
    const uint32_t sbase = smem_u32(smem);
    float* rmax = reinterpret_cast<float*>(smem + RM_OFF);  // [32c][2wn][64row]

    const int t    = threadIdx.x;
    const int lane = t & 31;
    const int wid  = t >> 5;
    const int wm   = wid >> 1;      // 0..1
    const int wn   = wid & 1;       // 0..1
    const int mi2  = blockIdx.x >> 2;   // 0..63 : rows [mi2*64, +64)
    const int cg   = blockIdx.x & 3;
    const int gid  = lane >> 2;
    const int tig  = lane & 3;

    // ---- prologue: async-stage A half-tile + B0 (g0), B1 (g1)
    {
        const char* gA = g_Qh + (size_t)(mi2 >> 1) * 32768 + (size_t)(mi2 & 1) * 16384;
        const char* gB = g_Ph + (size_t)(cg * 32) * 32768;
        #pragma unroll
        for (int j = 0; j < 8; ++j) {
            int off = j * 2048 + t * 16;
            cp16(sbase + A_OFF + off, gA + off);
        }
        #pragma unroll
        for (int j = 0; j < 16; ++j) {
            int off = j * 2048 + t * 16;
            cp16(sbase + B_OFF(0) + off, gB + off);
        }
        CP_COMMIT();
        const char* gB1 = gB + 32768;
        #pragma unroll
        for (int j = 0; j < 16; ++j) {
            int off = j * 2048 + t * 16;
            cp16(sbase + B_OFF(1) + off, gB1 + off);
        }
        CP_COMMIT();
    }
    CP_WAIT(1);
    __syncthreads();

    // ---- A fragments -> registers (once; local rows 0..63)
    uint32_t aF[2][8][4];
    {
        const int rA = wm * 32 + (lane & 15);
        const int kqA = lane >> 4;
        #pragma unroll
        for (int mt = 0; mt < 2; ++mt) {
            const int row = rA + mt * 16;
            const uint32_t rowbase = sbase + A_OFF + row * 256;
            #pragma unroll
            for (int ks = 0; ks < 8; ++ks) {
                uint32_t addr = rowbase + (((2 * ks + kqA) ^ (row & 7)) << 4);
                ldsm4(aF[mt][ks][0], aF[mt][ks][1], aF[mt][ks][2], aF[mt][ks][3], addr);
            }
        }
    }

    const int rBl = (lane & 7) + ((lane >> 4) << 3);
    const int kqB = (lane >> 3) & 1;
    const int rowB0 = wn * 64 + rBl;
    const int rowB1 = wn * 64 + 16 + rBl;
    const int rowB2 = wn * 64 + 32 + rBl;
    const int rowB3 = wn * 64 + 48 + rBl;

    for (int i = 0; i < 32; ++i) {
        const uint32_t Bbase = sbase + B_OFF(i & 1);

        float acc[2][8][4];
        #pragma unroll
        for (int mt = 0; mt < 2; ++mt)
            #pragma unroll
            for (int nt = 0; nt < 8; ++nt)
                #pragma unroll
                for (int r = 0; r < 4; ++r) acc[mt][nt][r] = 0.0f;

        uint32_t bF[2][4][4];
        {
            uint32_t a0 = Bbase + rowB0 * 256 + ((kqB ^ (rowB0 & 7)) << 4);
            uint32_t a1 = Bbase + rowB1 * 256 + ((kqB ^ (rowB1 & 7)) << 4);
            uint32_t a2 = Bbase + rowB2 * 256 + ((kqB ^ (rowB2 & 7)) << 4);
            uint32_t a3 = Bbase + rowB3 * 256 + ((kqB ^ (rowB3 & 7)) << 4);
            ldsm4(bF[0][0][0], bF[0][0][1], bF[0][0][2], bF[0][0][3], a0);
            ldsm4(bF[0][1][0], bF[0][1][1], bF[0][1][2], bF[0][1][3], a1);
            ldsm4(bF[0][2][0], bF[0][2][1], bF[0][2][2], bF[0][2][3], a2);
            ldsm4(bF[0][3][0], bF[0][3][1], bF[0][3][2], bF[0][3][3], a3);
        }
        #pragma unroll
        for (int ks = 0; ks < 8; ++ks) {
            const int cur = ks & 1, nxt = cur ^ 1;
            if (ks < 7) {
                const int ku = 2 * (ks + 1) + kqB;
                uint32_t a0 = Bbase + rowB0 * 256 + ((ku ^ (rowB0 & 7)) << 4);
                uint32_t a1 = Bbase + rowB1 * 256 + ((ku ^ (rowB1 & 7)) << 4);
                uint32_t a2 = Bbase + rowB2 * 256 + ((ku ^ (rowB2 & 7)) << 4);
                uint32_t a3 = Bbase + rowB3 * 256 + ((ku ^ (rowB3 & 7)) << 4);
                ldsm4(bF[nxt][0][0], bF[nxt][0][1], bF[nxt][0][2], bF[nxt][0][3], a0);
                ldsm4(bF[nxt][1][0], bF[nxt][1][1], bF[nxt][1][2], bF[nxt][1][3], a1);
                ldsm4(bF[nxt][2][0], bF[nxt][2][1], bF[nxt][2][2], bF[nxt][2][3], a2);
                ldsm4(bF[nxt][3][0], bF[nxt][3][1], bF[nxt][3][2], bF[nxt][3][3], a3);
            }
            #pragma unroll
            for (int np = 0; np < 4; ++np)
                #pragma unroll
                for (int mt = 0; mt < 2; ++mt) {
                    mma16(acc[mt][2 * np],     aF[mt][ks], bF[cur][np][0], bF[cur][np][1]);
                    mma16(acc[mt][2 * np + 1], aF[mt][ks], bF[cur][np][2], bF[cur][np][3]);
                }
        }

        // ---- per-row max over this warp's 64 n-cols -> private rmax slab
        float* rbuf = rmax + (i * 2 + wn) * 64;
        #pragma unroll
        for (int mt = 0; mt < 2; ++mt) {
            float m0 = acc[mt][0][0], m1 = acc[mt][0][2];
            #pragma unroll
            for (int nt = 0; nt < 8; ++nt) {
                m0 = fmaxf(m0, fmaxf(acc[mt][nt][0], acc[mt][nt][1]));
                m1 = fmaxf(m1, fmaxf(acc[mt][nt][2], acc[mt][nt][3]));
            }
            m0 = fmaxf(m0, __shfl_xor_sync(0xffffffffu, m0, 1));
            m0 = fmaxf(m0, __shfl_xor_sync(0xffffffffu, m0, 2));
            m1 = fmaxf(m1, __shfl_xor_sync(0xffffffffu, m1, 1));
            m1 = fmaxf(m1, __shfl_xor_sync(0xffffffffu, m1, 2));
            if (tig == 0) {
                rbuf[wm * 32 + mt * 16 + gid]     = m0;
                rbuf[wm * 32 + mt * 16 + 8 + gid] = m1;
            }
        }

        // ---- recycle: wait for next buf's data, barrier, refill cur buf
        CP_WAIT(0);
        __syncthreads();
        if (i + 2 < 32) {
            const char* gB = g_Ph + (size_t)(cg * 32 + i + 2) * 32768;
            #pragma unroll
            for (int j = 0; j < 16; ++j) {
                int off = j * 2048 + t * 16;
                cp16(sbase + B_OFF(i & 1) + off, gB + off);
            }
            CP_COMMIT();
        }
    }

    // ---- combine: warp w handles 8 c's; lane = s-row within each b
    {
        const int b0 = mi2 * 2, b1 = mi2 * 2 + 1;
        #pragma unroll
        for (int cl = 0; cl < 8; ++cl) {
            const int ci = wid * 8 + cl;
            const float* r = rmax + ci * 128;   // [wn0:64][wn1:64]
            float v0 = fmaxf(r[lane],      r[64 + lane]);
            float v1 = fmaxf(r[32 + lane], r[96 + lane]);
            #pragma unroll
            for (int off = 16; off; off >>= 1) {
                v0 += __shfl_xor_sync(0xffffffffu, v0, off);
                v1 += __shfl_xor_sync(0xffffffffu, v1, off);
            }
            if (lane == 0) {
                const int c = cg * 32 + ci;
                g_scores[b0 * Bn + c] = v0;
                g_scores[b1 * Bn + c] = v1;
            }
        }
    }

    // ---- last CTA computes the loss
    __syncthreads();
    __threadfence();
    __shared__ unsigned s_rank;
    if (t == 0) s_rank = atomicAdd(&g_cnt, 1);
    __syncthreads();
    if (s_rank != 255) return;
    if (t == 0) atomicExch(&g_cnt, 0);
    __threadfence();

    // 128 threads: thread t = row t of the score matrix
    const float4* rp = reinterpret_cast<const float4*>(&g_scores[t * Bn]);
    float m = -CUDART_INF_F, diag = 0.0f;
    #pragma unroll
    for (int k4 = 0; k4 < 32; ++k4) {
        float4 v = rp[k4];
        m = fmaxf(m, fmaxf(fmaxf(v.x, v.y), fmaxf(v.z, v.w)));
        int cb = k4 * 4;
        if (t == cb + 0) diag = v.x;
        if (t == cb + 1) diag = v.y;
        if (t == cb + 2) diag = v.z;
        if (t == cb + 3) diag = v.w;
    }
    float s = 0.0f;
    #pragma unroll
    for (int k4 = 0; k4 < 32; ++k4) {
        float4 v = rp[k4];
        s += expf(50.0f * (v.x - m)) + expf(50.0f * (v.y - m)) +
             expf(50.0f * (v.z - m)) + expf(50.0f * (v.w - m));
    }
    float term = 50.0f * diag - (50.0f * m + logf(s));

    float* sred = rmax;  // reuse smem
    #pragma unroll
    for (int off = 16; off; off >>= 1) term += __shfl_xor_sync(0xffffffffu, term, off);
    if (lane == 0) sred[wid] = term;
    __syncthreads();
    if (t == 0) out[0] = -(sred[0] + sred[1] + sred[2] + sred[3]) / 128.0f;
}

// ---------------------------------------------------------------------------
extern "C" void kernel_launch(void* const* d_in, const int* in_sizes, int n_in,
                              void* d_out, int out_size)
{
    const float* Q = (const float*)d_in[0];  // [128, 32, 128]
    const float* P = (const float*)d_in[1];  // [128, 128, 128]
    float* out = (float*)d_out;

    cudaFuncSetAttribute(colbert_fused,
                         cudaFuncAttributeMaxDynamicSharedMemorySize, SMEM_BYTES);
    colbert_convert<<<160, 256>>>(Q, P);
    colbert_fused<<<256, 128, SMEM_BYTES>>>(out);
}

// round 8
// speedup vs baseline: 1.4635x; 1.0111x over previous
#include <cuda_runtime.h>
#include <cuda_fp16.h>
#include <math_constants.h>
#include <cstdint>

#define Bn 128
#define Hn 128

__device__ float    g_scores[Bn * Bn];
__device__ unsigned g_cnt = 0;
// Pre-converted, pre-swizzled fp16 tiles (tile = 128 rows x 256B swizzled)
__device__ __align__(16) char g_Qh[32 * 32768];    // 1MB: 32 mi-tiles
__device__ __align__(16) char g_Ph[128 * 32768];   // 4MB: 128 c-tiles
// Deferred per-warp row-max scratch: [cta][c][wn][64]
__device__ __align__(16) float g_rmax[256 * 32 * 2 * 64];

// smem: B buf0 (32K) | B buf1 (32K) | B buf2 (32K, A overlaid in lower 16K
// during the prologue only)
#define B_OFF(b)   ((b) * 32768)
#define A_OFF      65536
#define SMEM_BYTES (3 * 32768 + 128)

__device__ __forceinline__ uint32_t smem_u32(const void* p) {
    uint32_t a;
    asm("{ .reg .u64 t; cvta.to.shared.u64 t, %1; cvt.u32.u64 %0, t; }" : "=r"(a) : "l"(p));
    return a;
}
__device__ __forceinline__ void cp16(uint32_t sm, const void* g) {
    asm volatile("cp.async.cg.shared.global [%0], [%1], 16;" :: "r"(sm), "l"(g));
}
#define CP_COMMIT() asm volatile("cp.async.commit_group;" ::: "memory")
#define CP_WAIT(n)  asm volatile("cp.async.wait_group %0;" :: "n"(n) : "memory")

__device__ __forceinline__ void ldsm4(uint32_t& r0, uint32_t& r1, uint32_t& r2, uint32_t& r3,
                                      uint32_t addr) {
    asm volatile("ldmatrix.sync.aligned.m8n8.x4.shared.b16 {%0,%1,%2,%3}, [%4];"
                 : "=r"(r0), "=r"(r1), "=r"(r2), "=r"(r3) : "r"(addr));
}
__device__ __forceinline__ void mma16(float* d, const uint32_t* a, uint32_t b0, uint32_t b1) {
    asm volatile(
        "mma.sync.aligned.m16n8k16.row.col.f32.f16.f16.f32 "
        "{%0,%1,%2,%3}, {%4,%5,%6,%7}, {%8,%9}, {%0,%1,%2,%3};"
        : "+f"(d[0]), "+f"(d[1]), "+f"(d[2]), "+f"(d[3])
        : "r"(a[0]), "r"(a[1]), "r"(a[2]), "r"(a[3]), "r"(b0), "r"(b1));
}

// ---------------------------------------------------------------------------
// Pre-kernel: fp32 [128 x 128] tile -> fp16 swizzled (row*256B, unit^(row&7)).
// ---------------------------------------------------------------------------
extern "C" __global__ void __launch_bounds__(256)
colbert_convert(const float* __restrict__ Q, const float* __restrict__ P)
{
    const int bid = blockIdx.x, t = threadIdx.x;
    const float4* src;
    char* dst;
    if (bid < 128) { src = reinterpret_cast<const float4*>(P) + (size_t)bid * 4096; dst = g_Ph + (size_t)bid * 32768; }
    else           { src = reinterpret_cast<const float4*>(Q) + (size_t)(bid - 128) * 4096; dst = g_Qh + (size_t)(bid - 128) * 32768; }
    #pragma unroll
    for (int j = 0; j < 16; ++j) {
        int f4 = j * 256 + t;
        float4 v = src[f4];
        int row = f4 >> 5, c4 = f4 & 31;
        __half2 h0 = __floats2half2_rn(v.x, v.y);
        __half2 h1 = __floats2half2_rn(v.z, v.w);
        uint2 w;
        w.x = *reinterpret_cast<uint32_t*>(&h0);
        w.y = *reinterpret_cast<uint32_t*>(&h1);
        int off = row * 256 + ((((c4 >> 1) ^ (row & 7))) << 4) + ((c4 & 1) << 3);
        *reinterpret_cast<uint2*>(dst + off) = w;
    }
}

// ---------------------------------------------------------------------------
// Main: 256 CTAs x 128 threads, 2 CTAs/SM. CTA (mi2=bid>>2: 64 A-rows, cg=bid&3).
// 4 warps: wm=wid>>1 (M=32 = one b), wn=wid&1 (N=64 half).
// 3-deep cp.async B pipeline; zero-wait boundaries; rmax deferred to global.
// ---------------------------------------------------------------------------
extern "C" __global__ void __launch_bounds__(128, 2)
colbert_fused(float* __restrict__ out)
{
    extern __shared__ __align__(128) char smem[];
    const uint32_t sbase = smem_u32(smem);

    const int t    = threadIdx.x;
    const int lane = t & 31;
    const int wid  = t >> 5;
    const int wm   = wid >> 1;
    const int wn   = wid & 1;
    const int mi2  = blockIdx.x >> 2;   // rows [mi2*64, +64)
    const int cg   = blockIdx.x & 3;
    const int gid  = lane >> 2;
    const int tig  = lane & 3;

    // ---- prologue
    const char* gB0 = g_Ph + (size_t)(cg * 32) * 32768;
    {
        const char* gA = g_Qh + (size_t)(mi2 >> 1) * 32768 + (size_t)(mi2 & 1) * 16384;
        #pragma unroll
        for (int j = 0; j < 8; ++j) {          // A -> buf2 lower half
            int off = j * 2048 + t * 16;
            cp16(sbase + A_OFF + off, gA + off);
        }
        #pragma unroll
        for (int j = 0; j < 16; ++j) {         // tile0 -> buf0
            int off = j * 2048 + t * 16;
            cp16(sbase + B_OFF(0) + off, gB0 + off);
        }
        CP_COMMIT();                            // G0 = {A, tile0}
        #pragma unroll
        for (int j = 0; j < 16; ++j) {         // tile1 -> buf1
            int off = j * 2048 + t * 16;
            cp16(sbase + B_OFF(1) + off, gB0 + 32768 + off);
        }
        CP_COMMIT();                            // G1 = {tile1}
    }
    CP_WAIT(1);          // G0 complete
    __syncthreads();

    // ---- A fragments -> registers (from buf2 region, before tile2 lands)
    uint32_t aF[2][8][4];
    {
        const int rA = wm * 32 + (lane & 15);
        const int kqA = lane >> 4;
        #pragma unroll
        for (int mt = 0; mt < 2; ++mt) {
            const int row = rA + mt * 16;
            const uint32_t rowbase = sbase + A_OFF + row * 256;
            #pragma unroll
            for (int ks = 0; ks < 8; ++ks) {
                uint32_t addr = rowbase + (((2 * ks + kqA) ^ (row & 7)) << 4);
                ldsm4(aF[mt][ks][0], aF[mt][ks][1], aF[mt][ks][2], aF[mt][ks][3], addr);
            }
        }
    }
    __syncthreads();     // all aF reads done before tile2 overwrites A region
    {
        #pragma unroll
        for (int j = 0; j < 16; ++j) {         // tile2 -> buf2
            int off = j * 2048 + t * 16;
            cp16(sbase + B_OFF(2) + off, gB0 + 2 * 32768 + off);
        }
        CP_COMMIT();                            // G2 = {tile2}
    }

    // per-thread B row bases
    const int rBl = (lane & 7) + ((lane >> 4) << 3);
    const int kqB = (lane >> 3) & 1;
    int rOff[4], rSw[4];
    #pragma unroll
    for (int np = 0; np < 4; ++np) {
        int row = wn * 64 + np * 16 + rBl;
        rOff[np] = row * 256;
        rSw[np]  = row & 7;
    }

    uint32_t bF[2][4][4];
    // initial bF[0] from buf0 (tile0 ready)
    #pragma unroll
    for (int np = 0; np < 4; ++np) {
        uint32_t addr = sbase + B_OFF(0) + rOff[np] + (((kqB) ^ rSw[np]) << 4);
        ldsm4(bF[0][np][0], bF[0][np][1], bF[0][np][2], bF[0][np][3], addr);
    }

    for (int i = 0; i < 32; ++i) {
        const uint32_t Bbase = sbase + B_OFF(i % 3);

        float acc[2][8][4];
        #pragma unroll
        for (int mt = 0; mt < 2; ++mt)
            #pragma unroll
            for (int nt = 0; nt < 8; ++nt)
                #pragma unroll
                for (int r = 0; r < 4; ++r) acc[mt][nt][r] = 0.0f;

        #pragma unroll
        for (int ks = 0; ks < 8; ++ks) {
            const int cur = ks & 1, nxt = cur ^ 1;
            if (ks < 7) {
                const int ku = 2 * (ks + 1) + kqB;
                #pragma unroll
                for (int np = 0; np < 4; ++np) {
                    uint32_t addr = Bbase + rOff[np] + ((ku ^ rSw[np]) << 4);
                    ldsm4(bF[nxt][np][0], bF[nxt][np][1], bF[nxt][np][2], bF[nxt][np][3], addr);
                }
            }
            #pragma unroll
            for (int np = 0; np < 4; ++np)
                #pragma unroll
                for (int mt = 0; mt < 2; ++mt) {
                    mma16(acc[mt][2 * np],     aF[mt][ks], bF[cur][np][0], bF[cur][np][1]);
                    mma16(acc[mt][2 * np + 1], aF[mt][ks], bF[cur][np][2], bF[cur][np][3]);
                }
        }

        // ---- boundary: zero-wait recycle + next-iter bF0 prefetch
        if (i + 1 < 32) {
            if (i + 3 < 32) { CP_WAIT(1); } else { CP_WAIT(0); }
            __syncthreads();
            if (i + 3 < 32) {
                const char* gB = gB0 + (size_t)(i + 3) * 32768;
                #pragma unroll
                for (int j = 0; j < 16; ++j) {
                    int off = j * 2048 + t * 16;
                    cp16(sbase + B_OFF(i % 3) + off, gB + off);
                }
                CP_COMMIT();
            }
            const uint32_t Bnext = sbase + B_OFF((i + 1) % 3);
            #pragma unroll
            for (int np = 0; np < 4; ++np) {
                uint32_t addr = Bnext + rOff[np] + ((kqB ^ rSw[np]) << 4);
                ldsm4(bF[0][np][0], bF[0][np][1], bF[0][np][2], bF[0][np][3], addr);
            }
        }

        // ---- epilogue: per-row max over this warp's 64 n-cols -> global scratch
        float* gr = g_rmax + ((size_t)(blockIdx.x * 32 + i) * 2 + wn) * 64;
        #pragma unroll
        for (int mt = 0; mt < 2; ++mt) {
            float m0 = acc[mt][0][0], m1 = acc[mt][0][2];
            #pragma unroll
            for (int nt = 0; nt < 8; ++nt) {
                m0 = fmaxf(m0, fmaxf(acc[mt][nt][0], acc[mt][nt][1]));
                m1 = fmaxf(m1, fmaxf(acc[mt][nt][2], acc[mt][nt][3]));
            }
            m0 = fmaxf(m0, __shfl_xor_sync(0xffffffffu, m0, 1));
            m0 = fmaxf(m0, __shfl_xor_sync(0xffffffffu, m0, 2));
            m1 = fmaxf(m1, __shfl_xor_sync(0xffffffffu, m1, 1));
            m1 = fmaxf(m1, __shfl_xor_sync(0xffffffffu, m1, 2));
            if (tig == 0) {
                gr[wm * 32 + mt * 16 + gid]     = m0;
                gr[wm * 32 + mt * 16 + 8 + gid] = m1;
            }
        }
    }

    __syncthreads();  // block-scope fence: all warps' g_rmax writes visible

    // ---- combine: warp w handles 8 c's; lane = s-row within each b
    {
        const int b0 = mi2 * 2, b1 = mi2 * 2 + 1;
        #pragma unroll
        for (int cl = 0; cl < 8; ++cl) {
            const int ci = wid * 8 + cl;
            const float* r = g_rmax + (size_t)(blockIdx.x * 32 + ci) * 128;
            float v0 = fmaxf(r[lane],      r[64 + lane]);
            float v1 = fmaxf(r[32 + lane], r[96 + lane]);
            #pragma unroll
            for (int off = 16; off; off >>= 1) {
                v0 += __shfl_xor_sync(0xffffffffu, v0, off);
                v1 += __shfl_xor_sync(0xffffffffu, v1, off);
            }
            if (lane == 0) {
                const int c = cg * 32 + ci;
                g_scores[b0 * Bn + c] = v0;
                g_scores[b1 * Bn + c] = v1;
            }
        }
    }

    // ---- last CTA computes the loss
    __syncthreads();
    __threadfence();
    __shared__ unsigned s_rank;
    if (t == 0) s_rank = atomicAdd(&g_cnt, 1);
    __syncthreads();
    if (s_rank != 255) return;
    if (t == 0) atomicExch(&g_cnt, 0);
    __threadfence();

    const float4* rp = reinterpret_cast<const float4*>(&g_scores[t * Bn]);
    float m = -CUDART_INF_F, diag = 0.0f;
    #pragma unroll
    for (int k4 = 0; k4 < 32; ++k4) {
        float4 v = rp[k4];
        m = fmaxf(m, fmaxf(fmaxf(v.x, v.y), fmaxf(v.z, v.w)));
        int cb = k4 * 4;
        if (t == cb + 0) diag = v.x;
        if (t == cb + 1) diag = v.y;
        if (t == cb + 2) diag = v.z;
        if (t == cb + 3) diag = v.w;
    }
    float s = 0.0f;
    #pragma unroll
    for (int k4 = 0; k4 < 32; ++k4) {
        float4 v = rp[k4];
        s += expf(50.0f * (v.x - m)) + expf(50.0f * (v.y - m)) +
             expf(50.0f * (v.z - m)) + expf(50.0f * (v.w - m));
    }
    float term = 50.0f * diag - (50.0f * m + logf(s));

    float* sred = reinterpret_cast<float*>(smem);
    #pragma unroll
    for (int off = 16; off; off >>= 1) term += __shfl_xor_sync(0xffffffffu, term, off);
    if (lane == 0) sred[wid] = term;
    __syncthreads();
    if (t == 0) out[0] = -(sred[0] + sred[1] + sred[2] + sred[3]) / 128.0f;
}

// ---------------------------------------------------------------------------
extern "C" void kernel_launch(void* const* d_in, const int* in_sizes, int n_in,
                              void* d_out, int out_size)
{
    const float* Q = (const float*)d_in[0];  // [128, 32, 128]
    const float* P = (const float*)d_in[1];  // [128, 128, 128]
    float* out = (float*)d_out;

    cudaFuncSetAttribute(colbert_fused,
                         cudaFuncAttributeMaxDynamicSharedMemorySize, SMEM_BYTES);
    colbert_convert<<<160, 256>>>(Q, P);
    colbert_fused<<<256, 128, SMEM_BYTES>>>(out);
}